// round 13
// baseline (speedup 1.0000x reference)
#include <cuda_runtime.h>
#include <cuda_fp16.h>
#include <mma.h>
#include <cstdint>

using namespace nvcuda;

#define NMAX 100000
#define EMAX 3200000
#define SCAN_B 512
#define NSCAN ((NMAX + SCAN_B - 1) / SCAN_B)   // 196

// Scratch (device globals -- no allocation allowed).
// g_cnt is zero at module load and re-zeroed at the end of every call
// (tail of k_agg2_final). g_cur is set to g_off by k_scan23 each call.
__device__ int     g_cnt[NMAX];
__device__ int     g_cur[NMAX];
__device__ float   g_dis[NMAX];
__device__ int     g_off[NMAX + 1];
__device__ int     g_bsum[NSCAN];
__device__ int     g_csr_src[EMAX];
__device__ __align__(16) __half2 g_h1s[NMAX * 32];  // 64 cols fp16 per row
__device__ __align__(16) __half  g_h2s[NMAX * 32];  // 32 cols fp16 per row

// ---------------------------------------------------------------------------
__global__ void k_count(const int* __restrict__ dst, int E) {
    int e = blockIdx.x * blockDim.x + threadIdx.x;
    if (e < E) atomicAdd(&g_cnt[dst[e]], 1);
}

// per-block sums of g_cnt
__global__ __launch_bounds__(SCAN_B) void k_scan1(int n) {
    __shared__ int s[SCAN_B];
    int t = threadIdx.x;
    int i = blockIdx.x * SCAN_B + t;
    s[t] = (i < n) ? g_cnt[i] : 0;
    __syncthreads();
    for (int d = SCAN_B / 2; d > 0; d >>= 1) {
        if (t < d) s[t] += s[t + d];
        __syncthreads();
    }
    if (t == 0) g_bsum[blockIdx.x] = s[0];
}

// merged scan2+scan3: every block locally scans the <=256 block sums, then
// scans its element slice. Fused: dis = rsqrt(cnt+1); g_cur = absolute offset.
__global__ __launch_bounds__(SCAN_B) void k_scan23(int n, int nb) {
    __shared__ int bs[256];
    __shared__ int s[SCAN_B];
    int t = threadIdx.x;

    if (t < 256) bs[t] = (t < nb) ? g_bsum[t] : 0;
    __syncthreads();
    for (int d = 1; d < 256; d <<= 1) {
        int x = 0;
        if (t < 256 && t >= d) x = bs[t - d];
        __syncthreads();
        if (t < 256) bs[t] += x;
        __syncthreads();
    }
    int boff = (blockIdx.x == 0) ? 0 : bs[blockIdx.x - 1];

    int i = blockIdx.x * SCAN_B + t;
    int v = (i < n) ? g_cnt[i] : 0;
    s[t] = v;
    __syncthreads();
    for (int d = 1; d < SCAN_B; d <<= 1) {
        int x = (t >= d) ? s[t - d] : 0;
        __syncthreads();
        s[t] += x;
        __syncthreads();
    }
    int incl = s[t] + boff;
    if (i < n) {
        int excl = incl - v;
        g_off[i] = excl;
        g_cur[i] = excl;            // absolute fill cursor
        if (i == n - 1) g_off[n] = incl;
        g_dis[i] = rsqrtf((float)(v + 1));
    }
}

// ---------------------------------------------------------------------------
// Heterogeneous kernel: CSR fill blocks interleaved with GEMM1 wmma blocks.
// Every 9th block (b % 9 == 0) is a GEMM block -> gemm tile b/9.
// Others are fill blocks -> fill slice b - b/9 - 1 (1 thread per edge).
// Both paths depend only on scan23 outputs and are mutually independent, so
// they overlap at the hardware level (LTS atomics || tensor/smem pipes).
#define XS_LD 136
#define W1_LD 72
__global__ __launch_bounds__(256) void k_fill_gemm1(
        const float* __restrict__ x, const float* __restrict__ W1,
        const int* __restrict__ src, const int* __restrict__ dst,
        int n, int E, int gemmBlocks) {
    __shared__ __align__(16) __half xs[64 * XS_LD];    // 17408 B
    __shared__ __align__(16) __half w1s[128 * W1_LD];  // 18432 B

    int b = blockIdx.x;
    int t = threadIdx.x;

    bool isGemm = (b % 9 == 0) && (b / 9 < gemmBlocks);
    if (!isGemm) {
        // ---- fill path: 1 thread per edge ----
        int fb = b - b / 9 - ((b % 9 == 0) ? 1 : 1);
        // count of gemm blocks <= b is b/9 + 1 when b%9==0... but isGemm
        // handles b%9==0; here b%9 != 0 (or b/9 >= gemmBlocks, impossible
        // given grid sizing). gemm blocks before b = b/9 + 1.
        fb = b - (b / 9) - 1;
        int e = fb * 256 + t;
        if (e < E) {
            int p = atomicAdd(&g_cur[dst[e]], 1);
            g_csr_src[p] = src[e];
        }
        return;
    }

    // ---- GEMM1 path: 64-row wmma tile ----
    int tile = b / 9;
    int rowbase = tile * 64;

    // stage A (x tile, 64 rows) fp16
    for (int i = t; i < 2048; i += 256) {
        int r = i >> 5, c4 = i & 31;
        __half2 h0, h1;
        if (rowbase + r < n) {
            float4 v = reinterpret_cast<const float4*>(
                x + (size_t)(rowbase + r) * 128)[c4];
            h0 = __floats2half2_rn(v.x, v.y);
            h1 = __floats2half2_rn(v.z, v.w);
        } else {
            h0 = __floats2half2_rn(0.f, 0.f);
            h1 = h0;
        }
        __half2* p = reinterpret_cast<__half2*>(&xs[r * XS_LD + c4 * 4]);
        p[0] = h0;
        p[1] = h1;
    }
    // stage B (W1) fp16
    for (int i = t; i < 2048; i += 256) {
        int k = i >> 4, c4 = i & 15;
        float4 v = reinterpret_cast<const float4*>(W1)[k * 16 + c4];
        __half2* p = reinterpret_cast<__half2*>(&w1s[k * W1_LD + c4 * 4]);
        p[0] = __floats2half2_rn(v.x, v.y);
        p[1] = __floats2half2_rn(v.z, v.w);
    }
    __syncthreads();

    // 8 warps; C is 64x64 = 4x4 tiles of 16x16. warp w: row tile w&3,
    // col tiles (w>>2)*16 and +32. One A-frag shared by both.
    int w = t >> 5;
    int mrow = (w & 3) * 16;
    int ncol = (w >> 2) * 16;

    wmma::fragment<wmma::accumulator, 16, 16, 16, float> acc0, acc1;
    wmma::fill_fragment(acc0, 0.0f);
    wmma::fill_fragment(acc1, 0.0f);
#pragma unroll
    for (int k0 = 0; k0 < 8; k0++) {
        wmma::fragment<wmma::matrix_a, 16, 16, 16, __half, wmma::row_major> fa;
        wmma::fragment<wmma::matrix_b, 16, 16, 16, __half, wmma::row_major> fb0, fb1;
        wmma::load_matrix_sync(fa, &xs[mrow * XS_LD + k0 * 16], XS_LD);
        wmma::load_matrix_sync(fb0, &w1s[(k0 * 16) * W1_LD + ncol], W1_LD);
        wmma::load_matrix_sync(fb1, &w1s[(k0 * 16) * W1_LD + ncol + 32], W1_LD);
        wmma::mma_sync(acc0, fa, fb0, acc0);
        wmma::mma_sync(acc1, fa, fb1, acc1);
    }
    __syncthreads();  // all A reads done before C overwrites xs

    float* cs = reinterpret_cast<float*>(xs);  // 64x64 fp32 = 16384 B
    wmma::store_matrix_sync(&cs[mrow * 64 + ncol], acc0, 64, wmma::mem_row_major);
    wmma::store_matrix_sync(&cs[mrow * 64 + ncol + 32], acc1, 64, wmma::mem_row_major);
    __syncthreads();

    // epilogue: scale by dis, convert fp16, store (64 rows x 16 float4)
    for (int i = t; i < 1024; i += 256) {
        int r = i >> 4, c4 = i & 15;
        int gr = rowbase + r;
        if (gr < n) {
            float d = g_dis[gr];
            float4 v = reinterpret_cast<const float4*>(cs)[i];
            g_h1s[(size_t)gr * 32 + 2 * c4]     = __floats2half2_rn(v.x * d, v.y * d);
            g_h1s[(size_t)gr * 32 + 2 * c4 + 1] = __floats2half2_rn(v.z * d, v.w * d);
        }
    }
}

// ---------------------------------------------------------------------------
__device__ __forceinline__ void acc8_add(float* acc, uint4 v) {
    const __half2* hv = reinterpret_cast<const __half2*>(&v);
    float2 f0 = __half22float2(hv[0]);
    float2 f1 = __half22float2(hv[1]);
    float2 f2 = __half22float2(hv[2]);
    float2 f3 = __half22float2(hv[3]);
    acc[0] += f0.x; acc[1] += f0.y;
    acc[2] += f1.x; acc[3] += f1.y;
    acc[4] += f2.x; acc[5] += f2.y;
    acc[6] += f3.x; acc[7] += f3.y;
}

// agg1 + relu + tensor-core layer2. 512 threads = 16 warps = 16 nodes/block.
#define HS_LD 72
#define W2_LD 40
__global__ __launch_bounds__(512) void k_agg1_l2(const float* __restrict__ b1,
                                                 const float* __restrict__ W2,
                                                 int n) {
    __shared__ __align__(16) __half hs[16 * HS_LD];
    __shared__ __align__(16) __half w2s[64 * W2_LD];
    __shared__ __align__(16) float  cs[16 * 32];

    int t = threadIdx.x;
    if (t < 512) {
        int k = t >> 3, c4 = t & 7;
        float4 v = reinterpret_cast<const float4*>(W2)[t];
        __half2* p = reinterpret_cast<__half2*>(&w2s[k * W2_LD + c4 * 4]);
        p[0] = __floats2half2_rn(v.x, v.y);
        p[1] = __floats2half2_rn(v.z, v.w);
    }

    int wid = t >> 5, lane = t & 31;
    int node = blockIdx.x * 16 + wid;
    int g = lane >> 3;
    int c = lane & 7;

    float h[8] = {0.f, 0.f, 0.f, 0.f, 0.f, 0.f, 0.f, 0.f};
    if (node < n) {
        int beg = g_off[node], end = g_off[node + 1];
        int deg = end - beg;

        float acc[8] = {0.f, 0.f, 0.f, 0.f, 0.f, 0.f, 0.f, 0.f};
        int nfull = deg & ~7;
        int e0 = beg;
        for (; e0 < beg + nfull; e0 += 8) {
            int sA = g_csr_src[e0 + g];
            int sB = g_csr_src[e0 + 4 + g];
            uint4 vA = *(reinterpret_cast<const uint4*>(g_h1s + (size_t)sA * 32) + c);
            uint4 vB = *(reinterpret_cast<const uint4*>(g_h1s + (size_t)sB * 32) + c);
            acc8_add(acc, vA);
            acc8_add(acc, vB);
        }
        for (; e0 < end; e0 += 4) {
            int ee = e0 + g;
            if (ee < end) {
                int s = g_csr_src[ee];
                uint4 v = *(reinterpret_cast<const uint4*>(g_h1s + (size_t)s * 32) + c);
                acc8_add(acc, v);
            }
        }
#pragma unroll
        for (int r = 0; r < 8; r++) {
            acc[r] += __shfl_xor_sync(0xffffffffu, acc[r], 8);
            acc[r] += __shfl_xor_sync(0xffffffffu, acc[r], 16);
        }

        float di = g_dis[node];
        float self[8] = {0.f, 0.f, 0.f, 0.f, 0.f, 0.f, 0.f, 0.f};
        {
            uint4 sv = *(reinterpret_cast<const uint4*>(g_h1s + (size_t)node * 32) + c);
            acc8_add(self, sv);
        }
        float4 bA = reinterpret_cast<const float4*>(b1)[2 * c];
        float4 bB = reinterpret_cast<const float4*>(b1)[2 * c + 1];
        float bb[8] = {bA.x, bA.y, bA.z, bA.w, bB.x, bB.y, bB.z, bB.w};
#pragma unroll
        for (int r = 0; r < 8; r++)
            h[r] = fmaxf((acc[r] + self[r]) * di + bb[r], 0.f);
    }
    if (g == 0) {
        __half2* p = reinterpret_cast<__half2*>(&hs[wid * HS_LD + c * 8]);
        p[0] = __floats2half2_rn(h[0], h[1]);
        p[1] = __floats2half2_rn(h[2], h[3]);
        p[2] = __floats2half2_rn(h[4], h[5]);
        p[3] = __floats2half2_rn(h[6], h[7]);
    }
    __syncthreads();

    // layer2 GEMM: warps 0,1 compute C[16x32] = hs[16x64] @ w2s[64x32]
    if (wid < 2) {
        wmma::fragment<wmma::accumulator, 16, 16, 16, float> acc;
        wmma::fill_fragment(acc, 0.0f);
#pragma unroll
        for (int k0 = 0; k0 < 4; k0++) {
            wmma::fragment<wmma::matrix_a, 16, 16, 16, __half, wmma::row_major> fa;
            wmma::fragment<wmma::matrix_b, 16, 16, 16, __half, wmma::row_major> fb;
            wmma::load_matrix_sync(fa, &hs[k0 * 16], HS_LD);
            wmma::load_matrix_sync(fb, &w2s[(k0 * 16) * W2_LD + wid * 16], W2_LD);
            wmma::mma_sync(acc, fa, fb, acc);
        }
        wmma::store_matrix_sync(&cs[wid * 16], acc, 32, wmma::mem_row_major);
    }
    __syncthreads();

    if (t < 256) {
        int nd = t >> 4, c2 = t & 15;
        int gnode = blockIdx.x * 16 + nd;
        if (gnode < n) {
            float di = g_dis[gnode];
            float2 v = reinterpret_cast<const float2*>(cs)[nd * 16 + c2];
            reinterpret_cast<__half2*>(g_h2s)[(size_t)gnode * 16 + c2] =
                __floats2half2_rn(v.x * di, v.y * di);
        }
    }
}

// ---------------------------------------------------------------------------
__device__ __forceinline__ void acc4_add(float* acc, uint2 v) {
    const __half2* hv = reinterpret_cast<const __half2*>(&v);
    float2 f0 = __half22float2(hv[0]);
    float2 f1 = __half22float2(hv[1]);
    acc[0] += f0.x; acc[1] += f0.y;
    acc[2] += f1.x; acc[3] += f1.y;
}

// agg2 + final FC. One warp per node; wide loads. Tail: zero g_cnt.
__global__ __launch_bounds__(256) void k_agg2_final(const float* __restrict__ b2,
                                                    const float* __restrict__ Wfc,
                                                    const float* __restrict__ bfc,
                                                    float* __restrict__ out, int n) {
    int tid = blockIdx.x * blockDim.x + threadIdx.x;
    int warp = tid >> 5;
    if (warp < n) {
        int lane = threadIdx.x & 31;
        int g = lane >> 3;
        int c = lane & 7;
        int beg = g_off[warp], end = g_off[warp + 1];
        int deg = end - beg;

        float acc[4] = {0.f, 0.f, 0.f, 0.f};
        int nfull = deg & ~7;
        int e0 = beg;
        for (; e0 < beg + nfull; e0 += 8) {
            int sA = g_csr_src[e0 + g];
            int sB = g_csr_src[e0 + 4 + g];
            uint2 vA = *(reinterpret_cast<const uint2*>(g_h2s + (size_t)sA * 32) + c);
            uint2 vB = *(reinterpret_cast<const uint2*>(g_h2s + (size_t)sB * 32) + c);
            acc4_add(acc, vA);
            acc4_add(acc, vB);
        }
        for (; e0 < end; e0 += 4) {
            int ee = e0 + g;
            if (ee < end) {
                int s = g_csr_src[ee];
                uint2 v = *(reinterpret_cast<const uint2*>(g_h2s + (size_t)s * 32) + c);
                acc4_add(acc, v);
            }
        }
#pragma unroll
        for (int r = 0; r < 4; r++) {
            acc[r] += __shfl_xor_sync(0xffffffffu, acc[r], 8);
            acc[r] += __shfl_xor_sync(0xffffffffu, acc[r], 16);
        }

        float di = g_dis[warp];
        float self[4] = {0.f, 0.f, 0.f, 0.f};
        {
            uint2 sv = *(reinterpret_cast<const uint2*>(g_h2s + (size_t)warp * 32) + c);
            acc4_add(self, sv);
        }
        float4 bv = reinterpret_cast<const float4*>(b2)[c];
        float4 wv = reinterpret_cast<const float4*>(Wfc)[c];
        float o = fmaxf((acc[0] + self[0]) * di + bv.x, 0.f) * wv.x
                + fmaxf((acc[1] + self[1]) * di + bv.y, 0.f) * wv.y
                + fmaxf((acc[2] + self[2]) * di + bv.z, 0.f) * wv.z
                + fmaxf((acc[3] + self[3]) * di + bv.w, 0.f) * wv.w;
        o += __shfl_xor_sync(0xffffffffu, o, 1);
        o += __shfl_xor_sync(0xffffffffu, o, 2);
        o += __shfl_xor_sync(0xffffffffu, o, 4);
        if (lane == 0) out[warp] = o + bfc[0];
    }
    // tail: re-zero degree counters for the next call (coalesced)
    if (tid < n) g_cnt[tid] = 0;
}

// ---------------------------------------------------------------------------
extern "C" void kernel_launch(void* const* d_in, const int* in_sizes, int n_in,
                              void* d_out, int out_size) {
    const float* x   = (const float*)d_in[0];
    const int*   ei  = (const int*)d_in[1];
    const float* W1  = (const float*)d_in[2];
    const float* b1  = (const float*)d_in[3];
    const float* W2  = (const float*)d_in[4];
    const float* b2  = (const float*)d_in[5];
    const float* Wfc = (const float*)d_in[6];
    const float* bfc = (const float*)d_in[7];
    float* out = (float*)d_out;

    int N = in_sizes[0] / 128;
    int E = in_sizes[1] / 2;
    const int* src = ei;
    const int* dst = ei + E;

    int rb64   = (N + 63) / 64;          // gemm tiles (1563)
    int fillB  = (E + 255) / 256;        // fill blocks (12500)
    int eb256  = fillB;
    int nscan  = (N + SCAN_B - 1) / SCAN_B;
    int totalB = rb64 + fillB;           // heterogeneous grid (14063)

    k_count<<<eb256, 256>>>(dst, E);
    k_scan1<<<nscan, SCAN_B>>>(N);
    k_scan23<<<nscan, SCAN_B>>>(N, nscan);
    k_fill_gemm1<<<totalB, 256>>>(x, W1, src, dst, N, E, rb64);
    k_agg1_l2<<<(N + 15) / 16, 512>>>(b1, W2, N);
    k_agg2_final<<<(N * 32 + 255) / 256, 256>>>(b2, Wfc, bfc, out, N);
}

// round 14
// speedup vs baseline: 1.0768x; 1.0768x over previous
#include <cuda_runtime.h>
#include <cuda_fp16.h>
#include <mma.h>
#include <cstdint>

using namespace nvcuda;

#define NMAX 100000
#define EMAX 3200000
#define SCAN_B 512
#define NSCAN ((NMAX + SCAN_B - 1) / SCAN_B)   // 196

// Scratch (device globals -- no allocation allowed).
// g_cnt is zero at module load and re-zeroed at the end of every call
// (tail of k_agg2_final). g_cur is set to g_off by k_scan23 each call.
__device__ int     g_cnt[NMAX];
__device__ int     g_cur[NMAX];
__device__ float   g_dis[NMAX];
__device__ int     g_off[NMAX + 1];
__device__ int     g_bsum[NSCAN];
__device__ int     g_csr_src[EMAX];
__device__ __align__(16) __half2 g_h1s[NMAX * 32];  // 64 cols fp16 per row
__device__ __align__(16) __half  g_h2s[NMAX * 32];  // 32 cols fp16 per row

// ---------------------------------------------------------------------------
__global__ void k_count(const int* __restrict__ dst, int E) {
    int e = blockIdx.x * blockDim.x + threadIdx.x;
    if (e < E) atomicAdd(&g_cnt[dst[e]], 1);
}

// per-block sums of g_cnt
__global__ __launch_bounds__(SCAN_B) void k_scan1(int n) {
    __shared__ int s[SCAN_B];
    int t = threadIdx.x;
    int i = blockIdx.x * SCAN_B + t;
    s[t] = (i < n) ? g_cnt[i] : 0;
    __syncthreads();
    for (int d = SCAN_B / 2; d > 0; d >>= 1) {
        if (t < d) s[t] += s[t + d];
        __syncthreads();
    }
    if (t == 0) g_bsum[blockIdx.x] = s[0];
}

// merged scan2+scan3: every block locally scans the <=256 block sums, then
// scans its element slice. Fused: dis = rsqrt(cnt+1); g_cur = absolute offset.
__global__ __launch_bounds__(SCAN_B) void k_scan23(int n, int nb) {
    __shared__ int bs[256];
    __shared__ int s[SCAN_B];
    int t = threadIdx.x;

    if (t < 256) bs[t] = (t < nb) ? g_bsum[t] : 0;
    __syncthreads();
    for (int d = 1; d < 256; d <<= 1) {
        int x = 0;
        if (t < 256 && t >= d) x = bs[t - d];
        __syncthreads();
        if (t < 256) bs[t] += x;
        __syncthreads();
    }
    int boff = (blockIdx.x == 0) ? 0 : bs[blockIdx.x - 1];

    int i = blockIdx.x * SCAN_B + t;
    int v = (i < n) ? g_cnt[i] : 0;
    s[t] = v;
    __syncthreads();
    for (int d = 1; d < SCAN_B; d <<= 1) {
        int x = (t >= d) ? s[t - d] : 0;
        __syncthreads();
        s[t] += x;
        __syncthreads();
    }
    int incl = s[t] + boff;
    if (i < n) {
        int excl = incl - v;
        g_off[i] = excl;
        g_cur[i] = excl;            // absolute fill cursor
        if (i == n - 1) g_off[n] = incl;
        g_dis[i] = rsqrtf((float)(v + 1));
    }
}

// CSR fill: ONE thread per edge -- max TLP hides the L2-atomic latency.
__global__ void k_fill(const int* __restrict__ src,
                       const int* __restrict__ dst, int E) {
    int e = blockIdx.x * blockDim.x + threadIdx.x;
    if (e < E) {
        int p = atomicAdd(&g_cur[dst[e]], 1);
        g_csr_src[p] = src[e];
    }
}

// ---------------------------------------------------------------------------
// GEMM1 (wmma), 64-row tiles: h1s[64x64] = (x[64x128] @ W1[128x64]) * dis
#define XS_LD 136
#define W1_LD 72
__global__ __launch_bounds__(256) void k_gemm1(
        const float* __restrict__ x, const float* __restrict__ W1, int n) {
    __shared__ __align__(16) __half xs[64 * XS_LD];    // 17408 B
    __shared__ __align__(16) __half w1s[128 * W1_LD];  // 18432 B

    int t = threadIdx.x;
    int rowbase = blockIdx.x * 64;

    // stage A (x tile, 64 rows) fp16
    for (int i = t; i < 2048; i += 256) {
        int r = i >> 5, c4 = i & 31;
        __half2 h0, h1;
        if (rowbase + r < n) {
            float4 v = reinterpret_cast<const float4*>(
                x + (size_t)(rowbase + r) * 128)[c4];
            h0 = __floats2half2_rn(v.x, v.y);
            h1 = __floats2half2_rn(v.z, v.w);
        } else {
            h0 = __floats2half2_rn(0.f, 0.f);
            h1 = h0;
        }
        __half2* p = reinterpret_cast<__half2*>(&xs[r * XS_LD + c4 * 4]);
        p[0] = h0;
        p[1] = h1;
    }
    // stage B (W1) fp16
    for (int i = t; i < 2048; i += 256) {
        int k = i >> 4, c4 = i & 15;
        float4 v = reinterpret_cast<const float4*>(W1)[k * 16 + c4];
        __half2* p = reinterpret_cast<__half2*>(&w1s[k * W1_LD + c4 * 4]);
        p[0] = __floats2half2_rn(v.x, v.y);
        p[1] = __floats2half2_rn(v.z, v.w);
    }
    __syncthreads();

    // 8 warps; C is 64x64 = 4x4 tiles of 16x16. warp w: row tile w&3,
    // col tiles (w>>2)*16 and +32. One A-frag shared by both.
    int w = t >> 5;
    int mrow = (w & 3) * 16;
    int ncol = (w >> 2) * 16;

    wmma::fragment<wmma::accumulator, 16, 16, 16, float> acc0, acc1;
    wmma::fill_fragment(acc0, 0.0f);
    wmma::fill_fragment(acc1, 0.0f);
#pragma unroll
    for (int k0 = 0; k0 < 8; k0++) {
        wmma::fragment<wmma::matrix_a, 16, 16, 16, __half, wmma::row_major> fa;
        wmma::fragment<wmma::matrix_b, 16, 16, 16, __half, wmma::row_major> fb0, fb1;
        wmma::load_matrix_sync(fa, &xs[mrow * XS_LD + k0 * 16], XS_LD);
        wmma::load_matrix_sync(fb0, &w1s[(k0 * 16) * W1_LD + ncol], W1_LD);
        wmma::load_matrix_sync(fb1, &w1s[(k0 * 16) * W1_LD + ncol + 32], W1_LD);
        wmma::mma_sync(acc0, fa, fb0, acc0);
        wmma::mma_sync(acc1, fa, fb1, acc1);
    }
    __syncthreads();  // all A reads done before C overwrites xs

    float* cs = reinterpret_cast<float*>(xs);  // 64x64 fp32 = 16384 B
    wmma::store_matrix_sync(&cs[mrow * 64 + ncol], acc0, 64, wmma::mem_row_major);
    wmma::store_matrix_sync(&cs[mrow * 64 + ncol + 32], acc1, 64, wmma::mem_row_major);
    __syncthreads();

    // epilogue: scale by dis, convert fp16, store (64 rows x 16 float4)
    for (int i = t; i < 1024; i += 256) {
        int r = i >> 4, c4 = i & 15;
        int gr = rowbase + r;
        if (gr < n) {
            float d = g_dis[gr];
            float4 v = reinterpret_cast<const float4*>(cs)[i];
            g_h1s[(size_t)gr * 32 + 2 * c4]     = __floats2half2_rn(v.x * d, v.y * d);
            g_h1s[(size_t)gr * 32 + 2 * c4 + 1] = __floats2half2_rn(v.z * d, v.w * d);
        }
    }
}

// ---------------------------------------------------------------------------
__device__ __forceinline__ void acc8_add(float* acc, uint4 v) {
    const __half2* hv = reinterpret_cast<const __half2*>(&v);
    float2 f0 = __half22float2(hv[0]);
    float2 f1 = __half22float2(hv[1]);
    float2 f2 = __half22float2(hv[2]);
    float2 f3 = __half22float2(hv[3]);
    acc[0] += f0.x; acc[1] += f0.y;
    acc[2] += f1.x; acc[3] += f1.y;
    acc[4] += f2.x; acc[5] += f2.y;
    acc[6] += f3.x; acc[7] += f3.y;
}

// agg1 + relu + tensor-core layer2. 512 threads = 16 warps = 16 nodes/block.
#define HS_LD 72
#define W2_LD 40
__global__ __launch_bounds__(512) void k_agg1_l2(const float* __restrict__ b1,
                                                 const float* __restrict__ W2,
                                                 int n) {
    __shared__ __align__(16) __half hs[16 * HS_LD];
    __shared__ __align__(16) __half w2s[64 * W2_LD];
    __shared__ __align__(16) float  cs[16 * 32];

    int t = threadIdx.x;
    if (t < 512) {
        int k = t >> 3, c4 = t & 7;
        float4 v = reinterpret_cast<const float4*>(W2)[t];
        __half2* p = reinterpret_cast<__half2*>(&w2s[k * W2_LD + c4 * 4]);
        p[0] = __floats2half2_rn(v.x, v.y);
        p[1] = __floats2half2_rn(v.z, v.w);
    }

    int wid = t >> 5, lane = t & 31;
    int node = blockIdx.x * 16 + wid;
    int g = lane >> 3;
    int c = lane & 7;

    float h[8] = {0.f, 0.f, 0.f, 0.f, 0.f, 0.f, 0.f, 0.f};
    if (node < n) {
        int beg = g_off[node], end = g_off[node + 1];
        int deg = end - beg;

        float acc[8] = {0.f, 0.f, 0.f, 0.f, 0.f, 0.f, 0.f, 0.f};
        int nfull = deg & ~7;
        int e0 = beg;
        for (; e0 < beg + nfull; e0 += 8) {
            int sA = g_csr_src[e0 + g];
            int sB = g_csr_src[e0 + 4 + g];
            uint4 vA = *(reinterpret_cast<const uint4*>(g_h1s + (size_t)sA * 32) + c);
            uint4 vB = *(reinterpret_cast<const uint4*>(g_h1s + (size_t)sB * 32) + c);
            acc8_add(acc, vA);
            acc8_add(acc, vB);
        }
        for (; e0 < end; e0 += 4) {
            int ee = e0 + g;
            if (ee < end) {
                int s = g_csr_src[ee];
                uint4 v = *(reinterpret_cast<const uint4*>(g_h1s + (size_t)s * 32) + c);
                acc8_add(acc, v);
            }
        }
#pragma unroll
        for (int r = 0; r < 8; r++) {
            acc[r] += __shfl_xor_sync(0xffffffffu, acc[r], 8);
            acc[r] += __shfl_xor_sync(0xffffffffu, acc[r], 16);
        }

        float di = g_dis[node];
        float self[8] = {0.f, 0.f, 0.f, 0.f, 0.f, 0.f, 0.f, 0.f};
        {
            uint4 sv = *(reinterpret_cast<const uint4*>(g_h1s + (size_t)node * 32) + c);
            acc8_add(self, sv);
        }
        float4 bA = reinterpret_cast<const float4*>(b1)[2 * c];
        float4 bB = reinterpret_cast<const float4*>(b1)[2 * c + 1];
        float bb[8] = {bA.x, bA.y, bA.z, bA.w, bB.x, bB.y, bB.z, bB.w};
#pragma unroll
        for (int r = 0; r < 8; r++)
            h[r] = fmaxf((acc[r] + self[r]) * di + bb[r], 0.f);
    }
    if (g == 0) {
        __half2* p = reinterpret_cast<__half2*>(&hs[wid * HS_LD + c * 8]);
        p[0] = __floats2half2_rn(h[0], h[1]);
        p[1] = __floats2half2_rn(h[2], h[3]);
        p[2] = __floats2half2_rn(h[4], h[5]);
        p[3] = __floats2half2_rn(h[6], h[7]);
    }
    __syncthreads();

    // layer2 GEMM: warps 0,1 compute C[16x32] = hs[16x64] @ w2s[64x32]
    if (wid < 2) {
        wmma::fragment<wmma::accumulator, 16, 16, 16, float> acc;
        wmma::fill_fragment(acc, 0.0f);
#pragma unroll
        for (int k0 = 0; k0 < 4; k0++) {
            wmma::fragment<wmma::matrix_a, 16, 16, 16, __half, wmma::row_major> fa;
            wmma::fragment<wmma::matrix_b, 16, 16, 16, __half, wmma::row_major> fb;
            wmma::load_matrix_sync(fa, &hs[k0 * 16], HS_LD);
            wmma::load_matrix_sync(fb, &w2s[(k0 * 16) * W2_LD + wid * 16], W2_LD);
            wmma::mma_sync(acc, fa, fb, acc);
        }
        wmma::store_matrix_sync(&cs[wid * 16], acc, 32, wmma::mem_row_major);
    }
    __syncthreads();

    if (t < 256) {
        int nd = t >> 4, c2 = t & 15;
        int gnode = blockIdx.x * 16 + nd;
        if (gnode < n) {
            float di = g_dis[gnode];
            float2 v = reinterpret_cast<const float2*>(cs)[nd * 16 + c2];
            reinterpret_cast<__half2*>(g_h2s)[(size_t)gnode * 16 + c2] =
                __floats2half2_rn(v.x * di, v.y * di);
        }
    }
}

// ---------------------------------------------------------------------------
__device__ __forceinline__ void acc4_add(float* acc, uint2 v) {
    const __half2* hv = reinterpret_cast<const __half2*>(&v);
    float2 f0 = __half22float2(hv[0]);
    float2 f1 = __half22float2(hv[1]);
    acc[0] += f0.x; acc[1] += f0.y;
    acc[2] += f1.x; acc[3] += f1.y;
}

// agg2 + final FC. One warp per node; wide loads. Tail: zero g_cnt.
__global__ __launch_bounds__(256) void k_agg2_final(const float* __restrict__ b2,
                                                    const float* __restrict__ Wfc,
                                                    const float* __restrict__ bfc,
                                                    float* __restrict__ out, int n) {
    int tid = blockIdx.x * blockDim.x + threadIdx.x;
    int warp = tid >> 5;
    if (warp < n) {
        int lane = threadIdx.x & 31;
        int g = lane >> 3;
        int c = lane & 7;
        int beg = g_off[warp], end = g_off[warp + 1];
        int deg = end - beg;

        float acc[4] = {0.f, 0.f, 0.f, 0.f};
        int nfull = deg & ~7;
        int e0 = beg;
        for (; e0 < beg + nfull; e0 += 8) {
            int sA = g_csr_src[e0 + g];
            int sB = g_csr_src[e0 + 4 + g];
            uint2 vA = *(reinterpret_cast<const uint2*>(g_h2s + (size_t)sA * 32) + c);
            uint2 vB = *(reinterpret_cast<const uint2*>(g_h2s + (size_t)sB * 32) + c);
            acc4_add(acc, vA);
            acc4_add(acc, vB);
        }
        for (; e0 < end; e0 += 4) {
            int ee = e0 + g;
            if (ee < end) {
                int s = g_csr_src[ee];
                uint2 v = *(reinterpret_cast<const uint2*>(g_h2s + (size_t)s * 32) + c);
                acc4_add(acc, v);
            }
        }
#pragma unroll
        for (int r = 0; r < 4; r++) {
            acc[r] += __shfl_xor_sync(0xffffffffu, acc[r], 8);
            acc[r] += __shfl_xor_sync(0xffffffffu, acc[r], 16);
        }

        float di = g_dis[warp];
        float self[4] = {0.f, 0.f, 0.f, 0.f};
        {
            uint2 sv = *(reinterpret_cast<const uint2*>(g_h2s + (size_t)warp * 32) + c);
            acc4_add(self, sv);
        }
        float4 bv = reinterpret_cast<const float4*>(b2)[c];
        float4 wv = reinterpret_cast<const float4*>(Wfc)[c];
        float o = fmaxf((acc[0] + self[0]) * di + bv.x, 0.f) * wv.x
                + fmaxf((acc[1] + self[1]) * di + bv.y, 0.f) * wv.y
                + fmaxf((acc[2] + self[2]) * di + bv.z, 0.f) * wv.z
                + fmaxf((acc[3] + self[3]) * di + bv.w, 0.f) * wv.w;
        o += __shfl_xor_sync(0xffffffffu, o, 1);
        o += __shfl_xor_sync(0xffffffffu, o, 2);
        o += __shfl_xor_sync(0xffffffffu, o, 4);
        if (lane == 0) out[warp] = o + bfc[0];
    }
    // tail: re-zero degree counters for the next call (coalesced)
    if (tid < n) g_cnt[tid] = 0;
}

// ---------------------------------------------------------------------------
extern "C" void kernel_launch(void* const* d_in, const int* in_sizes, int n_in,
                              void* d_out, int out_size) {
    const float* x   = (const float*)d_in[0];
    const int*   ei  = (const int*)d_in[1];
    const float* W1  = (const float*)d_in[2];
    const float* b1  = (const float*)d_in[3];
    const float* W2  = (const float*)d_in[4];
    const float* b2  = (const float*)d_in[5];
    const float* Wfc = (const float*)d_in[6];
    const float* bfc = (const float*)d_in[7];
    float* out = (float*)d_out;

    int N = in_sizes[0] / 128;
    int E = in_sizes[1] / 2;
    const int* src = ei;
    const int* dst = ei + E;

    int rb64  = (N + 63) / 64;
    int fillB = (E + 255) / 256;
    int nscan = (N + SCAN_B - 1) / SCAN_B;

    // fork-join resources (created per call; intentionally NOT destroyed --
    // destroying a forked stream/event during graph capture would invalidate
    // the capture. kernel_launch is only invoked a handful of times.)
    cudaStream_t s1 = 0;
    cudaEvent_t eFork = 0, eJoin = 0;
    bool forked = (cudaStreamCreateWithFlags(&s1, cudaStreamNonBlocking) == cudaSuccess);
    if (forked) forked = (cudaEventCreateWithFlags(&eFork, cudaEventDisableTiming) == cudaSuccess);
    if (forked) forked = (cudaEventCreateWithFlags(&eJoin, cudaEventDisableTiming) == cudaSuccess);

    k_count<<<fillB, 256>>>(dst, E);
    k_scan1<<<nscan, SCAN_B>>>(N);
    k_scan23<<<nscan, SCAN_B>>>(N, nscan);

    if (forked) {
        // parallel branches: fill on s1, gemm1 on the capture stream
        cudaEventRecord(eFork, 0);
        cudaStreamWaitEvent(s1, eFork, 0);
        k_fill<<<fillB, 256, 0, s1>>>(src, dst, E);
        k_gemm1<<<rb64, 256>>>(x, W1, N);
        cudaEventRecord(eJoin, s1);
        cudaStreamWaitEvent(0, eJoin, 0);
    } else {
        k_fill<<<fillB, 256>>>(src, dst, E);
        k_gemm1<<<rb64, 256>>>(x, W1, N);
    }

    k_agg1_l2<<<(N + 15) / 16, 512>>>(b1, W2, N);
    k_agg2_final<<<(N * 32 + 255) / 256, 256>>>(b2, Wfc, bfc, out, N);
}

// round 17
// speedup vs baseline: 1.0978x; 1.0195x over previous
#include <cuda_runtime.h>
#include <cuda_fp16.h>
#include <mma.h>
#include <cstdint>

using namespace nvcuda;

#define NMAX 100000
#define EMAX 3200000
#define SCAN_B 512
#define NSCAN ((NMAX + SCAN_B - 1) / SCAN_B)   // 196

// Scratch (device globals -- no allocation allowed).
// g_cnt is zero at module load and re-zeroed at the end of every call
// (tail of k_agg2_final).
__device__ int     g_cnt[NMAX];
__device__ float   g_dis[NMAX];
__device__ int     g_off[NMAX + 1];
__device__ int     g_bsum[NSCAN];
__device__ int     g_rank[EMAX];     // edge's rank within its dst bucket
__device__ int     g_csr_src[EMAX];
__device__ __align__(16) __half2 g_h1s[NMAX * 32];  // 64 cols fp16 per row
__device__ __align__(16) __half  g_h2s[NMAX * 32];  // 32 cols fp16 per row

// ---------------------------------------------------------------------------
// count + rank: the atomic's return value IS the edge's bucket rank.
__global__ void k_count(const int* __restrict__ dst, int E) {
    int e = blockIdx.x * blockDim.x + threadIdx.x;
    if (e < E) g_rank[e] = atomicAdd(&g_cnt[dst[e]], 1);
}

// per-block sums of g_cnt
__global__ __launch_bounds__(SCAN_B) void k_scan1(int n) {
    __shared__ int s[SCAN_B];
    int t = threadIdx.x;
    int i = blockIdx.x * SCAN_B + t;
    s[t] = (i < n) ? g_cnt[i] : 0;
    __syncthreads();
    for (int d = SCAN_B / 2; d > 0; d >>= 1) {
        if (t < d) s[t] += s[t + d];
        __syncthreads();
    }
    if (t == 0) g_bsum[blockIdx.x] = s[0];
}

// merged scan2+scan3: every block locally scans the <=256 block sums, then
// scans its element slice. Fused: dis = rsqrt(cnt+1).
__global__ __launch_bounds__(SCAN_B) void k_scan23(int n, int nb) {
    __shared__ int bs[256];
    __shared__ int s[SCAN_B];
    int t = threadIdx.x;

    if (t < 256) bs[t] = (t < nb) ? g_bsum[t] : 0;
    __syncthreads();
    for (int d = 1; d < 256; d <<= 1) {
        int x = 0;
        if (t < 256 && t >= d) x = bs[t - d];
        __syncthreads();
        if (t < 256) bs[t] += x;
        __syncthreads();
    }
    int boff = (blockIdx.x == 0) ? 0 : bs[blockIdx.x - 1];

    int i = blockIdx.x * SCAN_B + t;
    int v = (i < n) ? g_cnt[i] : 0;
    s[t] = v;
    __syncthreads();
    for (int d = 1; d < SCAN_B; d <<= 1) {
        int x = (t >= d) ? s[t - d] : 0;
        __syncthreads();
        s[t] += x;
        __syncthreads();
    }
    int incl = s[t] + boff;
    if (i < n) {
        g_off[i] = incl - v;
        if (i == n - 1) g_off[n] = incl;
        g_dis[i] = rsqrtf((float)(v + 1));
    }
}

// CSR fill, ATOMIC-FREE: slot = off[dst] + precomputed rank.
__global__ void k_fill(const int* __restrict__ src,
                       const int* __restrict__ dst, int E) {
    int e = blockIdx.x * blockDim.x + threadIdx.x;
    if (e < E) {
        g_csr_src[g_off[dst[e]] + g_rank[e]] = src[e];
    }
}

// ---------------------------------------------------------------------------
// GEMM1 (wmma), 64-row tiles: h1s[64x64] = (x[64x128] @ W1[128x64]) * dis
#define XS_LD 136
#define W1_LD 72
__global__ __launch_bounds__(256) void k_gemm1(
        const float* __restrict__ x, const float* __restrict__ W1, int n) {
    __shared__ __align__(16) __half xs[64 * XS_LD];    // 17408 B
    __shared__ __align__(16) __half w1s[128 * W1_LD];  // 18432 B

    int t = threadIdx.x;
    int rowbase = blockIdx.x * 64;

    // stage A (x tile, 64 rows) fp16
    for (int i = t; i < 2048; i += 256) {
        int r = i >> 5, c4 = i & 31;
        __half2 h0, h1;
        if (rowbase + r < n) {
            float4 v = reinterpret_cast<const float4*>(
                x + (size_t)(rowbase + r) * 128)[c4];
            h0 = __floats2half2_rn(v.x, v.y);
            h1 = __floats2half2_rn(v.z, v.w);
        } else {
            h0 = __floats2half2_rn(0.f, 0.f);
            h1 = h0;
        }
        __half2* p = reinterpret_cast<__half2*>(&xs[r * XS_LD + c4 * 4]);
        p[0] = h0;
        p[1] = h1;
    }
    // stage B (W1) fp16
    for (int i = t; i < 2048; i += 256) {
        int k = i >> 4, c4 = i & 15;
        float4 v = reinterpret_cast<const float4*>(W1)[k * 16 + c4];
        __half2* p = reinterpret_cast<__half2*>(&w1s[k * W1_LD + c4 * 4]);
        p[0] = __floats2half2_rn(v.x, v.y);
        p[1] = __floats2half2_rn(v.z, v.w);
    }
    __syncthreads();

    // 8 warps; C is 64x64 = 4x4 tiles of 16x16. warp w: row tile w&3,
    // col tiles (w>>2)*16 and +32. One A-frag shared by both.
    int w = t >> 5;
    int mrow = (w & 3) * 16;
    int ncol = (w >> 2) * 16;

    wmma::fragment<wmma::accumulator, 16, 16, 16, float> acc0, acc1;
    wmma::fill_fragment(acc0, 0.0f);
    wmma::fill_fragment(acc1, 0.0f);
#pragma unroll
    for (int k0 = 0; k0 < 8; k0++) {
        wmma::fragment<wmma::matrix_a, 16, 16, 16, __half, wmma::row_major> fa;
        wmma::fragment<wmma::matrix_b, 16, 16, 16, __half, wmma::row_major> fb0, fb1;
        wmma::load_matrix_sync(fa, &xs[mrow * XS_LD + k0 * 16], XS_LD);
        wmma::load_matrix_sync(fb0, &w1s[(k0 * 16) * W1_LD + ncol], W1_LD);
        wmma::load_matrix_sync(fb1, &w1s[(k0 * 16) * W1_LD + ncol + 32], W1_LD);
        wmma::mma_sync(acc0, fa, fb0, acc0);
        wmma::mma_sync(acc1, fa, fb1, acc1);
    }
    __syncthreads();  // all A reads done before C overwrites xs

    float* cs = reinterpret_cast<float*>(xs);  // 64x64 fp32 = 16384 B
    wmma::store_matrix_sync(&cs[mrow * 64 + ncol], acc0, 64, wmma::mem_row_major);
    wmma::store_matrix_sync(&cs[mrow * 64 + ncol + 32], acc1, 64, wmma::mem_row_major);
    __syncthreads();

    // epilogue: scale by dis, convert fp16, store (64 rows x 16 float4)
    for (int i = t; i < 1024; i += 256) {
        int r = i >> 4, c4 = i & 15;
        int gr = rowbase + r;
        if (gr < n) {
            float d = g_dis[gr];
            float4 v = reinterpret_cast<const float4*>(cs)[i];
            g_h1s[(size_t)gr * 32 + 2 * c4]     = __floats2half2_rn(v.x * d, v.y * d);
            g_h1s[(size_t)gr * 32 + 2 * c4 + 1] = __floats2half2_rn(v.z * d, v.w * d);
        }
    }
}

// ---------------------------------------------------------------------------
__device__ __forceinline__ void acc8_add(float* acc, uint4 v) {
    const __half2* hv = reinterpret_cast<const __half2*>(&v);
    float2 f0 = __half22float2(hv[0]);
    float2 f1 = __half22float2(hv[1]);
    float2 f2 = __half22float2(hv[2]);
    float2 f3 = __half22float2(hv[3]);
    acc[0] += f0.x; acc[1] += f0.y;
    acc[2] += f1.x; acc[3] += f1.y;
    acc[4] += f2.x; acc[5] += f2.y;
    acc[6] += f3.x; acc[7] += f3.y;
}

// agg1 + relu + tensor-core layer2. 512 threads = 16 warps = 16 nodes/block.
#define HS_LD 72
#define W2_LD 40
__global__ __launch_bounds__(512) void k_agg1_l2(const float* __restrict__ b1,
                                                 const float* __restrict__ W2,
                                                 int n) {
    __shared__ __align__(16) __half hs[16 * HS_LD];
    __shared__ __align__(16) __half w2s[64 * W2_LD];
    __shared__ __align__(16) float  cs[16 * 32];

    int t = threadIdx.x;
    if (t < 512) {
        int k = t >> 3, c4 = t & 7;
        float4 v = reinterpret_cast<const float4*>(W2)[t];
        __half2* p = reinterpret_cast<__half2*>(&w2s[k * W2_LD + c4 * 4]);
        p[0] = __floats2half2_rn(v.x, v.y);
        p[1] = __floats2half2_rn(v.z, v.w);
    }

    int wid = t >> 5, lane = t & 31;
    int node = blockIdx.x * 16 + wid;
    int g = lane >> 3;
    int c = lane & 7;

    float h[8] = {0.f, 0.f, 0.f, 0.f, 0.f, 0.f, 0.f, 0.f};
    if (node < n) {
        int beg = g_off[node], end = g_off[node + 1];
        int deg = end - beg;

        float acc[8] = {0.f, 0.f, 0.f, 0.f, 0.f, 0.f, 0.f, 0.f};
        int nfull = deg & ~7;
        int e0 = beg;
        for (; e0 < beg + nfull; e0 += 8) {
            int sA = g_csr_src[e0 + g];
            int sB = g_csr_src[e0 + 4 + g];
            uint4 vA = *(reinterpret_cast<const uint4*>(g_h1s + (size_t)sA * 32) + c);
            uint4 vB = *(reinterpret_cast<const uint4*>(g_h1s + (size_t)sB * 32) + c);
            acc8_add(acc, vA);
            acc8_add(acc, vB);
        }
        for (; e0 < end; e0 += 4) {
            int ee = e0 + g;
            if (ee < end) {
                int s = g_csr_src[ee];
                uint4 v = *(reinterpret_cast<const uint4*>(g_h1s + (size_t)s * 32) + c);
                acc8_add(acc, v);
            }
        }
#pragma unroll
        for (int r = 0; r < 8; r++) {
            acc[r] += __shfl_xor_sync(0xffffffffu, acc[r], 8);
            acc[r] += __shfl_xor_sync(0xffffffffu, acc[r], 16);
        }

        float di = g_dis[node];
        float self[8] = {0.f, 0.f, 0.f, 0.f, 0.f, 0.f, 0.f, 0.f};
        {
            uint4 sv = *(reinterpret_cast<const uint4*>(g_h1s + (size_t)node * 32) + c);
            acc8_add(self, sv);
        }
        float4 bA = reinterpret_cast<const float4*>(b1)[2 * c];
        float4 bB = reinterpret_cast<const float4*>(b1)[2 * c + 1];
        float bb[8] = {bA.x, bA.y, bA.z, bA.w, bB.x, bB.y, bB.z, bB.w};
#pragma unroll
        for (int r = 0; r < 8; r++)
            h[r] = fmaxf((acc[r] + self[r]) * di + bb[r], 0.f);
    }
    if (g == 0) {
        __half2* p = reinterpret_cast<__half2*>(&hs[wid * HS_LD + c * 8]);
        p[0] = __floats2half2_rn(h[0], h[1]);
        p[1] = __floats2half2_rn(h[2], h[3]);
        p[2] = __floats2half2_rn(h[4], h[5]);
        p[3] = __floats2half2_rn(h[6], h[7]);
    }
    __syncthreads();

    // layer2 GEMM: warps 0,1 compute C[16x32] = hs[16x64] @ w2s[64x32]
    if (wid < 2) {
        wmma::fragment<wmma::accumulator, 16, 16, 16, float> acc;
        wmma::fill_fragment(acc, 0.0f);
#pragma unroll
        for (int k0 = 0; k0 < 4; k0++) {
            wmma::fragment<wmma::matrix_a, 16, 16, 16, __half, wmma::row_major> fa;
            wmma::fragment<wmma::matrix_b, 16, 16, 16, __half, wmma::row_major> fb;
            wmma::load_matrix_sync(fa, &hs[k0 * 16], HS_LD);
            wmma::load_matrix_sync(fb, &w2s[(k0 * 16) * W2_LD + wid * 16], W2_LD);
            wmma::mma_sync(acc, fa, fb, acc);
        }
        wmma::store_matrix_sync(&cs[wid * 16], acc, 32, wmma::mem_row_major);
    }
    __syncthreads();

    if (t < 256) {
        int nd = t >> 4, c2 = t & 15;
        int gnode = blockIdx.x * 16 + nd;
        if (gnode < n) {
            float di = g_dis[gnode];
            float2 v = reinterpret_cast<const float2*>(cs)[nd * 16 + c2];
            reinterpret_cast<__half2*>(g_h2s)[(size_t)gnode * 16 + c2] =
                __floats2half2_rn(v.x * di, v.y * di);
        }
    }
}

// ---------------------------------------------------------------------------
__device__ __forceinline__ void acc4_add(float* acc, uint2 v) {
    const __half2* hv = reinterpret_cast<const __half2*>(&v);
    float2 f0 = __half22float2(hv[0]);
    float2 f1 = __half22float2(hv[1]);
    acc[0] += f0.x; acc[1] += f0.y;
    acc[2] += f1.x; acc[3] += f1.y;
}

// agg2 + final FC. One warp per node; wide loads. Tail: zero g_cnt.
__global__ __launch_bounds__(256) void k_agg2_final(const float* __restrict__ b2,
                                                    const float* __restrict__ Wfc,
                                                    const float* __restrict__ bfc,
                                                    float* __restrict__ out, int n) {
    int tid = blockIdx.x * blockDim.x + threadIdx.x;
    int warp = tid >> 5;
    if (warp < n) {
        int lane = threadIdx.x & 31;
        int g = lane >> 3;
        int c = lane & 7;
        int beg = g_off[warp], end = g_off[warp + 1];
        int deg = end - beg;

        float acc[4] = {0.f, 0.f, 0.f, 0.f};
        int nfull = deg & ~7;
        int e0 = beg;
        for (; e0 < beg + nfull; e0 += 8) {
            int sA = g_csr_src[e0 + g];
            int sB = g_csr_src[e0 + 4 + g];
            uint2 vA = *(reinterpret_cast<const uint2*>(g_h2s + (size_t)sA * 32) + c);
            uint2 vB = *(reinterpret_cast<const uint2*>(g_h2s + (size_t)sB * 32) + c);
            acc4_add(acc, vA);
            acc4_add(acc, vB);
        }
        for (; e0 < end; e0 += 4) {
            int ee = e0 + g;
            if (ee < end) {
                int s = g_csr_src[ee];
                uint2 v = *(reinterpret_cast<const uint2*>(g_h2s + (size_t)s * 32) + c);
                acc4_add(acc, v);
            }
        }
#pragma unroll
        for (int r = 0; r < 4; r++) {
            acc[r] += __shfl_xor_sync(0xffffffffu, acc[r], 8);
            acc[r] += __shfl_xor_sync(0xffffffffu, acc[r], 16);
        }

        float di = g_dis[warp];
        float self[4] = {0.f, 0.f, 0.f, 0.f};
        {
            uint2 sv = *(reinterpret_cast<const uint2*>(g_h2s + (size_t)warp * 32) + c);
            acc4_add(self, sv);
        }
        float4 bv = reinterpret_cast<const float4*>(b2)[c];
        float4 wv = reinterpret_cast<const float4*>(Wfc)[c];
        float o = fmaxf((acc[0] + self[0]) * di + bv.x, 0.f) * wv.x
                + fmaxf((acc[1] + self[1]) * di + bv.y, 0.f) * wv.y
                + fmaxf((acc[2] + self[2]) * di + bv.z, 0.f) * wv.z
                + fmaxf((acc[3] + self[3]) * di + bv.w, 0.f) * wv.w;
        o += __shfl_xor_sync(0xffffffffu, o, 1);
        o += __shfl_xor_sync(0xffffffffu, o, 2);
        o += __shfl_xor_sync(0xffffffffu, o, 4);
        if (lane == 0) out[warp] = o + bfc[0];
    }
    // tail: re-zero degree counters for the next call (coalesced)
    if (tid < n) g_cnt[tid] = 0;
}

// ---------------------------------------------------------------------------
extern "C" void kernel_launch(void* const* d_in, const int* in_sizes, int n_in,
                              void* d_out, int out_size) {
    const float* x   = (const float*)d_in[0];
    const int*   ei  = (const int*)d_in[1];
    const float* W1  = (const float*)d_in[2];
    const float* b1  = (const float*)d_in[3];
    const float* W2  = (const float*)d_in[4];
    const float* b2  = (const float*)d_in[5];
    const float* Wfc = (const float*)d_in[6];
    const float* bfc = (const float*)d_in[7];
    float* out = (float*)d_out;

    int N = in_sizes[0] / 128;
    int E = in_sizes[1] / 2;
    const int* src = ei;
    const int* dst = ei + E;

    int rb64  = (N + 63) / 64;
    int fillB = (E + 255) / 256;
    int nscan = (N + SCAN_B - 1) / SCAN_B;

    // fork-join resources (created per call; intentionally NOT destroyed --
    // destroying a forked stream/event during graph capture would invalidate
    // the capture. kernel_launch is only invoked a handful of times.)
    cudaStream_t s1 = 0;
    cudaEvent_t eFork = 0, eJoin = 0;
    bool forked = (cudaStreamCreateWithFlags(&s1, cudaStreamNonBlocking) == cudaSuccess);
    if (forked) forked = (cudaEventCreateWithFlags(&eFork, cudaEventDisableTiming) == cudaSuccess);
    if (forked) forked = (cudaEventCreateWithFlags(&eJoin, cudaEventDisableTiming) == cudaSuccess);

    k_count<<<fillB, 256>>>(dst, E);
    k_scan1<<<nscan, SCAN_B>>>(N);
    k_scan23<<<nscan, SCAN_B>>>(N, nscan);

    if (forked) {
        // parallel branches: fill on s1, gemm1 on the capture stream
        cudaEventRecord(eFork, 0);
        cudaStreamWaitEvent(s1, eFork, 0);
        k_fill<<<fillB, 256, 0, s1>>>(src, dst, E);
        k_gemm1<<<rb64, 256>>>(x, W1, N);
        cudaEventRecord(eJoin, s1);
        cudaStreamWaitEvent(0, eJoin, 0);
    } else {
        k_fill<<<fillB, 256>>>(src, dst, E);
        k_gemm1<<<rb64, 256>>>(x, W1, N);
    }

    k_agg1_l2<<<(N + 15) / 16, 512>>>(b1, W2, N);
    k_agg2_final<<<(N * 32 + 255) / 256, 256>>>(b2, Wfc, bfc, out, N);
}